// round 15
// baseline (speedup 1.0000x reference)
#include <cuda_runtime.h>
#include <math.h>
#include <stdint.h>

#define BB 32
#define CC 256
#define HWD 96
#define ROW4 (HWD/4)         // 24 float4 per row
#define PLANE (HWD*HWD)      // 9216
#define PLANE_BYTES (PLANE*4)
#define NPLANES (BB*CC)      // 8192
#define KK 9
#define W2ROWS (CC*KK)       // 2304
#define NT 288

// scratch (no allocations allowed)
__device__ float g_pooled[NPLANES];
__device__ float g_h[BB*CC];
__device__ float g_wdyn[NPLANES * KK];

// ---------------------------------------------------------------------------
// pool(b): 1 block = 1 plane of batch b. Cached LDG warms L2 for conv(b).
// ---------------------------------------------------------------------------
__global__ __launch_bounds__(256) void pool_kernel(const float* __restrict__ x,
                                                   int p0) {
    const int plane = p0 + blockIdx.x;
    const float4* __restrict__ xp =
        reinterpret_cast<const float4*>(x + (size_t)plane * PLANE);
    float sum = 0.f;
#pragma unroll
    for (int it = 0; it < 9; ++it) {
        float4 v = xp[threadIdx.x + it * 256];
        sum += (v.x + v.y) + (v.z + v.w);
    }
#pragma unroll
    for (int o = 16; o > 0; o >>= 1)
        sum += __shfl_xor_sync(0xffffffffu, sum, o);
    __shared__ float ws[8];
    const int lane = threadIdx.x & 31, wid = threadIdx.x >> 5;
    if (lane == 0) ws[wid] = sum;
    __syncthreads();
    if (threadIdx.x == 0) {
        float t = 0.f;
#pragma unroll
        for (int i = 0; i < 8; ++i) t += ws[i];
        g_pooled[plane] = t * (1.0f / (float)PLANE);
    }
}

// ---------------------------------------------------------------------------
// dyn1(b): h = gelu(pooled[b] @ w1^T + b1). 32 wide blocks: 8 h-rows/block,
// each row's 256-dot split across 32 lanes (8 elems each) + shfl reduce.
// ---------------------------------------------------------------------------
__global__ __launch_bounds__(256) void dyn1_kernel(const float* __restrict__ w1,
                                                   const float* __restrict__ b1,
                                                   int b) {
    const int tid = threadIdx.x;
    __shared__ float ps[CC];
    if (tid < CC) ps[tid] = g_pooled[b * CC + tid];
    __syncthreads();

    const int row = blockIdx.x * 8 + (tid >> 5);   // 32*8 = 256 rows
    const int l   = tid & 31;
    const float4* __restrict__ wr =
        reinterpret_cast<const float4*>(w1 + (size_t)row * CC) + l * 2;
    const float4* __restrict__ pv =
        reinterpret_cast<const float4*>(ps) + l * 2;
    float acc = 0.f;
#pragma unroll
    for (int j = 0; j < 2; ++j) {
        float4 a = pv[j]; float4 w = wr[j];
        acc += a.x * w.x + a.y * w.y + a.z * w.z + a.w * w.w;
    }
#pragma unroll
    for (int o = 16; o > 0; o >>= 1)
        acc += __shfl_xor_sync(0xffffffffu, acc, o);
    if (l == 0) {
        float v = acc + b1[row];
        g_h[b * CC + row] = 0.5f * v * (1.0f + erff(v * 0.70710678118654752f));
    }
}

// ---------------------------------------------------------------------------
// dyn2(b): wdyn[b] = h[b] @ w2^T + b2. 64 blocks, 36 rows/block, 8-lane
// split dots + shfl. Reads precomputed h (1 KB) — no w1 replay.
// ---------------------------------------------------------------------------
__global__ __launch_bounds__(NT) void dyn2_kernel(const float* __restrict__ w2,
                                                  const float* __restrict__ b2,
                                                  int b) {
    const int rgrp = blockIdx.x;                   // 0..63
    const int tid  = threadIdx.x;
    __shared__ float hs[CC];
    if (tid < CC) hs[tid] = g_h[b * CC + tid];
    __syncthreads();

    const int row = rgrp * 36 + (tid >> 3);        // 64*36 = 2304 rows
    const int l8  = tid & 7;
    const float4* __restrict__ wr =
        reinterpret_cast<const float4*>(w2 + (size_t)row * CC) + l8 * 8;
    const float4* __restrict__ hv =
        reinterpret_cast<const float4*>(hs) + l8 * 8;
    float acc = 0.f;
#pragma unroll
    for (int j = 0; j < 8; ++j) {
        float4 a = hv[j]; float4 w = wr[j];
        acc += a.x * w.x + a.y * w.y + a.z * w.z + a.w * w.w;
    }
#pragma unroll
    for (int o = 4; o > 0; o >>= 1)
        acc += __shfl_xor_sync(0xffffffffu, acc, o);
    if (l8 == 0)
        g_wdyn[(size_t)b * W2ROWS + row] = acc + b2[row];
}

// ---------------------------------------------------------------------------
// conv(b): TMA bulk load plane -> smem (L2-hit: pool(b) just streamed it),
// register sliding window, streaming STG.128.
// ---------------------------------------------------------------------------
struct Row6 { float4 c; float l, r; };

__device__ __forceinline__ Row6 load_row_s(const float* __restrict__ s,
                                           int y, int xb, int x4) {
    Row6 o;
    const float* rp = s + y * HWD;
    o.c = *reinterpret_cast<const float4*>(rp + xb);
    o.l = (x4 == 0)        ? o.c.y : rp[xb - 1];      // reflect col -1 -> 1
    o.r = (x4 == ROW4 - 1) ? o.c.z : rp[xb + 4];      // reflect col 96 -> 94
    return o;
}

__device__ __forceinline__ void row_fma(float4& acc, const Row6& rr,
                                        float wl, float wc, float wr) {
    acc.x += rr.l   * wl + rr.c.x * wc + rr.c.y * wr;
    acc.y += rr.c.x * wl + rr.c.y * wc + rr.c.z * wr;
    acc.z += rr.c.y * wl + rr.c.z * wc + rr.c.w * wr;
    acc.w += rr.c.z * wl + rr.c.w * wc + rr.r   * wr;
}

__global__ __launch_bounds__(NT) void conv_kernel(const float* __restrict__ x,
                                                  float* __restrict__ out,
                                                  int p0) {
    const int plane = p0 + blockIdx.x;
    __shared__ __align__(16) float s[PLANE];
    __shared__ __align__(8) uint64_t mbar;
    const int tid = threadIdx.x;

    uint32_t s_u32, mbar_u32;
    asm("{ .reg .u64 t; cvta.to.shared.u64 t, %1; cvt.u32.u64 %0, t; }"
        : "=r"(s_u32) : "l"((const void*)s));
    asm("{ .reg .u64 t; cvta.to.shared.u64 t, %1; cvt.u32.u64 %0, t; }"
        : "=r"(mbar_u32) : "l"((const void*)&mbar));

    if (tid == 0) {
        asm volatile("mbarrier.init.shared.b64 [%0], 1;" :: "r"(mbar_u32) : "memory");
        asm volatile("fence.proxy.async.shared::cta;" ::: "memory");
        asm volatile("mbarrier.arrive.expect_tx.shared.b64 _, [%0], %1;"
                     :: "r"(mbar_u32), "r"((unsigned)PLANE_BYTES) : "memory");
        asm volatile(
            "cp.async.bulk.shared::cta.global.mbarrier::complete_tx::bytes "
            "[%0], [%1], %2, [%3];"
            :: "r"(s_u32), "l"(x + (size_t)plane * PLANE),
               "r"((unsigned)PLANE_BYTES), "r"(mbar_u32)
            : "memory");
    }

    float w[KK];
    const float* __restrict__ wd = g_wdyn + (size_t)plane * KK;
#pragma unroll
    for (int i = 0; i < KK; ++i) w[i] = wd[i];

    __syncthreads();
    {
        unsigned done = 0;
        while (!done) {
            asm volatile(
                "{\n .reg .pred p;\n"
                " mbarrier.try_wait.parity.acquire.cta.shared::cta.b64 p, [%1], %2, 0x989680;\n"
                " selp.b32 %0, 1, 0, p;\n}"
                : "=r"(done) : "r"(mbar_u32), "r"(0u) : "memory");
        }
    }

    const int x4 = tid % ROW4;
    const int cy = tid / ROW4;
    const int y0 = cy * 8;
    const int xb = x4 * 4;

    Row6 prev = load_row_s(s, (cy == 0) ? 1 : (y0 - 1), xb, x4);  // reflect -1 -> 1
    Row6 cur  = load_row_s(s, y0, xb, x4);

    float4* __restrict__ o4 =
        reinterpret_cast<float4*>(out + (size_t)plane * PLANE);

#pragma unroll
    for (int i = 0; i < 8; ++i) {
        const int y  = y0 + i;
        const int yn = (y == HWD - 1) ? HWD - 2 : y + 1;          // reflect 96 -> 94
        Row6 nxt = load_row_s(s, yn, xb, x4);
        float4 acc = make_float4(0.f, 0.f, 0.f, 0.f);
        row_fma(acc, prev, w[0], w[1], w[2]);
        row_fma(acc, cur,  w[3], w[4], w[5]);
        row_fma(acc, nxt,  w[6], w[7], w[8]);
        __stcs(&o4[y * ROW4 + x4], acc);                          // evict-first
        prev = cur; cur = nxt;
    }
}

// ---------------------------------------------------------------------------
// Stream/event topology, created once at load (host objects, no device mem).
// ---------------------------------------------------------------------------
static cudaStream_t sB, sC;
static cudaEvent_t  ePool[BB], eDyn[BB], eTail;
static struct GraphInit {
    GraphInit() {
        cudaStreamCreateWithFlags(&sB, cudaStreamNonBlocking);
        cudaStreamCreateWithFlags(&sC, cudaStreamNonBlocking);
        for (int i = 0; i < BB; ++i) {
            cudaEventCreateWithFlags(&ePool[i], cudaEventDisableTiming);
            cudaEventCreateWithFlags(&eDyn[i],  cudaEventDisableTiming);
        }
        cudaEventCreate(&eTail, cudaEventDisableTiming);
    }
} g_init;

extern "C" void kernel_launch(void* const* d_in, const int* in_sizes, int n_in,
                              void* d_out, int out_size) {
    const float* x  = (const float*)d_in[0];   // (32,256,96,96)
    const float* w1 = (const float*)d_in[1];   // (256,256)
    const float* b1 = (const float*)d_in[2];   // (256,)
    const float* w2 = (const float*)d_in[3];   // (2304,256)
    const float* b2 = (const float*)d_in[4];   // (2304,)
    float* out = (float*)d_out;

    // s0: per-batch pools in order; event after each batch.
    for (int b = 0; b < BB; ++b) {
        pool_kernel<<<CC, 256>>>(x, b * CC);
        cudaEventRecord(ePool[b], 0);
    }
    // sC: per-batch dyn chain (wide dyn1 -> dyn2), gated on that batch's pool.
    for (int b = 0; b < BB; ++b) {
        cudaStreamWaitEvent(sC, ePool[b], 0);
        dyn1_kernel<<<32, 256, 0, sC>>>(w1, b1, b);
        dyn2_kernel<<<64, NT, 0, sC>>>(w2, b2, b);
        cudaEventRecord(eDyn[b], sC);
    }
    // sB: per-batch conv, gated on that batch's dyn; x[b] is L2-resident.
    for (int b = 0; b < BB; ++b) {
        cudaStreamWaitEvent(sB, eDyn[b], 0);
        conv_kernel<<<CC, NT, 0, sB>>>(x, out, b * CC);
    }
    cudaEventRecord(eTail, sB);
    cudaStreamWaitEvent(0, eTail, 0);   // join back onto capture stream
}

// round 16
// speedup vs baseline: 2.2667x; 2.2667x over previous
#include <cuda_runtime.h>
#include <math.h>
#include <stdint.h>

#define BB 32
#define CC 256
#define HWD 96
#define ROW4 (HWD/4)         // 24 float4 per row
#define PLANE (HWD*HWD)      // 9216
#define PLANE_BYTES (PLANE*4)
#define NPLANES (BB*CC)      // 8192
#define KK 9
#define W2ROWS (CC*KK)       // 2304
#define NT 288

// scratch (no allocations allowed)
__device__ float g_pooled[NPLANES];
__device__ float g_h[BB*CC];

// ---------------------------------------------------------------------------
// Kernel 1: global average pool per (b,c) plane. 1 block = 1 plane.
// Measured at ~84% DRAM roofline (6.7 TB/s).
// ---------------------------------------------------------------------------
__global__ __launch_bounds__(256) void pool_kernel(const float* __restrict__ x) {
    const int plane = blockIdx.x;
    const float4* __restrict__ xp =
        reinterpret_cast<const float4*>(x + (size_t)plane * PLANE);
    float sum = 0.f;
#pragma unroll
    for (int it = 0; it < 9; ++it) {
        float4 v = xp[threadIdx.x + it * 256];
        sum += (v.x + v.y) + (v.z + v.w);
    }
#pragma unroll
    for (int o = 16; o > 0; o >>= 1)
        sum += __shfl_xor_sync(0xffffffffu, sum, o);
    __shared__ float ws[8];
    const int lane = threadIdx.x & 31, wid = threadIdx.x >> 5;
    if (lane == 0) ws[wid] = sum;
    __syncthreads();
    if (threadIdx.x == 0) {
        float t = 0.f;
#pragma unroll
        for (int i = 0; i < 8; ++i) t += ws[i];
        g_pooled[plane] = t * (1.0f / (float)PLANE);
    }
}

// ---------------------------------------------------------------------------
// Kernel 2: h = gelu(pooled @ w1^T + b1) only. grid = (32, BB).
// Block (rg, b): 8 h-rows, each row's 256-dot split across 32 lanes + shfl.
// ---------------------------------------------------------------------------
__global__ __launch_bounds__(256) void dynh_kernel(const float* __restrict__ w1,
                                                   const float* __restrict__ b1) {
    const int b   = blockIdx.y;
    const int tid = threadIdx.x;
    __shared__ float ps[CC];
    if (tid < CC) ps[tid] = g_pooled[b * CC + tid];
    __syncthreads();

    const int row = blockIdx.x * 8 + (tid >> 5);   // 32*8 = 256 rows
    const int l   = tid & 31;
    const float4* __restrict__ wr =
        reinterpret_cast<const float4*>(w1 + (size_t)row * CC) + l * 2;
    const float4* __restrict__ pv =
        reinterpret_cast<const float4*>(ps) + l * 2;
    float acc = 0.f;
#pragma unroll
    for (int j = 0; j < 2; ++j) {
        float4 a = pv[j]; float4 w = wr[j];
        acc += a.x * w.x + a.y * w.y + a.z * w.z + a.w * w.w;
    }
#pragma unroll
    for (int o = 16; o > 0; o >>= 1)
        acc += __shfl_xor_sync(0xffffffffu, acc, o);
    if (l == 0) {
        float v = acc + b1[row];
        g_h[b * CC + row] = 0.5f * v * (1.0f + erff(v * 0.70710678118654752f));
    }
}

// ---------------------------------------------------------------------------
// Kernel 3: conv with fused per-plane weight generation.
// While the TMA bulk load (plane -> smem) is in flight, the 288 threads
// (9 rows x 32 lanes) compute this plane's 9 dynamic weights:
//   w[kk] = b2[c*9+kk] + dot(h[b], w2[c*9+kk])      (w2, h are L2-hot)
// Then register-sliding 3x3 stencil + streaming STG.128.
// ---------------------------------------------------------------------------
struct Row6 { float4 c; float l, r; };

__device__ __forceinline__ Row6 load_row_s(const float* __restrict__ s,
                                           int y, int xb, int x4) {
    Row6 o;
    const float* rp = s + y * HWD;
    o.c = *reinterpret_cast<const float4*>(rp + xb);
    o.l = (x4 == 0)        ? o.c.y : rp[xb - 1];      // reflect col -1 -> 1
    o.r = (x4 == ROW4 - 1) ? o.c.z : rp[xb + 4];      // reflect col 96 -> 94
    return o;
}

__device__ __forceinline__ void row_fma(float4& acc, const Row6& rr,
                                        float wl, float wc, float wr) {
    acc.x += rr.l   * wl + rr.c.x * wc + rr.c.y * wr;
    acc.y += rr.c.x * wl + rr.c.y * wc + rr.c.z * wr;
    acc.z += rr.c.y * wl + rr.c.z * wc + rr.c.w * wr;
    acc.w += rr.c.z * wl + rr.c.w * wc + rr.r   * wr;
}

__global__ __launch_bounds__(NT) void conv_kernel(const float* __restrict__ x,
                                                  const float* __restrict__ w2,
                                                  const float* __restrict__ b2,
                                                  float* __restrict__ out) {
    const int plane = (NPLANES - 1) - blockIdx.x;     // reverse: L2 tail reuse
    const int b = plane >> 8;
    const int c = plane & 255;
    __shared__ __align__(16) float s[PLANE];
    __shared__ float sw[KK];
    __shared__ __align__(8) uint64_t mbar;
    const int tid = threadIdx.x;

    uint32_t s_u32, mbar_u32;
    asm("{ .reg .u64 t; cvta.to.shared.u64 t, %1; cvt.u32.u64 %0, t; }"
        : "=r"(s_u32) : "l"((const void*)s));
    asm("{ .reg .u64 t; cvta.to.shared.u64 t, %1; cvt.u32.u64 %0, t; }"
        : "=r"(mbar_u32) : "l"((const void*)&mbar));

    if (tid == 0) {
        asm volatile("mbarrier.init.shared.b64 [%0], 1;" :: "r"(mbar_u32) : "memory");
        asm volatile("fence.proxy.async.shared::cta;" ::: "memory");
        asm volatile("mbarrier.arrive.expect_tx.shared.b64 _, [%0], %1;"
                     :: "r"(mbar_u32), "r"((unsigned)PLANE_BYTES) : "memory");
        asm volatile(
            "cp.async.bulk.shared::cta.global.mbarrier::complete_tx::bytes "
            "[%0], [%1], %2, [%3];"
            :: "r"(s_u32), "l"(x + (size_t)plane * PLANE),
               "r"((unsigned)PLANE_BYTES), "r"(mbar_u32)
            : "memory");
    }

    // ---- fused dyn2: compute this plane's 9 weights while TMA flies --------
    {
        const int kk = tid >> 5;                      // 0..8 (tid<288 => all valid)
        const int l  = tid & 31;
        const int r  = c * KK + kk;
        const float4* __restrict__ wr =
            reinterpret_cast<const float4*>(w2 + (size_t)r * CC) + l * 2;
        const float4* __restrict__ hv =
            reinterpret_cast<const float4*>(g_h + b * CC) + l * 2;
        float acc = 0.f;
#pragma unroll
        for (int j = 0; j < 2; ++j) {
            float4 a = hv[j]; float4 w = wr[j];
            acc += a.x * w.x + a.y * w.y + a.z * w.z + a.w * w.w;
        }
#pragma unroll
        for (int o = 16; o > 0; o >>= 1)
            acc += __shfl_xor_sync(0xffffffffu, acc, o);
        if (l == 0) sw[kk] = acc + b2[r];
    }

    __syncthreads();   // sw visible; mbar.init visible before waits
    {
        unsigned done = 0;
        while (!done) {
            asm volatile(
                "{\n .reg .pred p;\n"
                " mbarrier.try_wait.parity.acquire.cta.shared::cta.b64 p, [%1], %2, 0x989680;\n"
                " selp.b32 %0, 1, 0, p;\n}"
                : "=r"(done) : "r"(mbar_u32), "r"(0u) : "memory");
        }
    }

    float w[KK];
#pragma unroll
    for (int i = 0; i < KK; ++i) w[i] = sw[i];        // LDS broadcast

    const int x4 = tid % ROW4;      // strip 0..23
    const int cy = tid / ROW4;      // chunk 0..11
    const int y0 = cy * 8;
    const int xb = x4 * 4;

    Row6 prev = load_row_s(s, (cy == 0) ? 1 : (y0 - 1), xb, x4);  // reflect -1 -> 1
    Row6 cur  = load_row_s(s, y0, xb, x4);

    float4* __restrict__ o4 =
        reinterpret_cast<float4*>(out + (size_t)plane * PLANE);

#pragma unroll
    for (int i = 0; i < 8; ++i) {
        const int y  = y0 + i;
        const int yn = (y == HWD - 1) ? HWD - 2 : y + 1;          // reflect 96 -> 94
        Row6 nxt = load_row_s(s, yn, xb, x4);
        float4 acc = make_float4(0.f, 0.f, 0.f, 0.f);
        row_fma(acc, prev, w[0], w[1], w[2]);
        row_fma(acc, cur,  w[3], w[4], w[5]);
        row_fma(acc, nxt,  w[6], w[7], w[8]);
        __stcs(&o4[y * ROW4 + x4], acc);                          // evict-first
        prev = cur; cur = nxt;
    }
}

// ---------------------------------------------------------------------------
extern "C" void kernel_launch(void* const* d_in, const int* in_sizes, int n_in,
                              void* d_out, int out_size) {
    const float* x  = (const float*)d_in[0];   // (32,256,96,96)
    const float* w1 = (const float*)d_in[1];   // (256,256)
    const float* b1 = (const float*)d_in[2];   // (256,)
    const float* w2 = (const float*)d_in[3];   // (2304,256)
    const float* b2 = (const float*)d_in[4];   // (2304,)
    float* out = (float*)d_out;

    pool_kernel<<<NPLANES, 256>>>(x);
    dynh_kernel<<<dim3(32, BB), 256>>>(w1, b1);
    conv_kernel<<<NPLANES, NT>>>(x, w2, b2, out);
}